// round 9
// baseline (speedup 1.0000x reference)
#include <cuda_runtime.h>
#include <cuda_fp16.h>
#include <math.h>

// Problem constants
#define Jc 166
#define Rc 864
#define Oc 8
#define Bc 128
#define BT 8            // batches per CTA (one per warp, warps 0-7)
#define TT 288          // threads per CTA (864/3), 9 warps
#define KR 3            // routes per thread in gen
#define RW 27           // routes per lane in routing (864/32)

#define W_ELEMS (Jc * Rc * Oc * 4)   // 4,589,568
#define U_ELEMS (Bc * Rc * 4)        //   442,368
#define NROUTES (Jc * Rc)            //   143,424

#define SMEM_BYTES (BT * Rc * 16)    // u_hat fp16-packed uint4: 110592 B

// fp16 copies of the inputs (static device buffers: no allocation)
// W16g layout: per route (j*Rc+r), 4 uint4; uint4 q holds half2 pairs
//   .x=(W[2q][0],W[2q+1][0]) .y=(i=1) .z=(i=2) .w=(i=3)
__device__ uint4  W16g[NROUTES * 4];   // 9.18 MB
__device__ __half u16g[U_ELEMS];       // 0.88 MB

__device__ __forceinline__ unsigned int pk2(float a, float b) {
    __half2 h = __floats2half2_rn(a, b);
    return *reinterpret_cast<unsigned int*>(&h);
}
__device__ __forceinline__ float2 up2(unsigned int v) {
    __half2 h = *reinterpret_cast<__half2*>(&v);
    return __half22float2(h);
}
__device__ __forceinline__ __half2 h2(unsigned int v) {
    return *reinterpret_cast<__half2*>(&v);
}
__device__ __forceinline__ unsigned int u32(__half2 v) {
    return *reinterpret_cast<unsigned int*>(&v);
}

// butterfly-reduce N floats across the warp (all lanes get result)
template<int N>
__device__ __forceinline__ void wredN(float* p) {
#pragma unroll
    for (int s = 16; s; s >>= 1)
#pragma unroll
        for (int q = 0; q < N; q++)
            p[q] += __shfl_xor_sync(0xffffffffu, p[q], s);
}

// ------------------- prep: fp32 -> fp16 (W o-pair-interleaved, u flat) -----
__global__ void __launch_bounds__(256)
prep_kernel(const float* __restrict__ W, const float* __restrict__ u)
{
    const int idx = blockIdx.x * blockDim.x + threadIdx.x;
    if (idx < NROUTES) {
        const float4* f4 = (const float4*)(W + (size_t)idx * 32);
#pragma unroll
        for (int q = 0; q < 4; q++) {
            const float4 lo = f4[2 * q];       // o = 2q,   i = 0..3
            const float4 hi = f4[2 * q + 1];   // o = 2q+1, i = 0..3
            uint4 o;
            o.x = pk2(lo.x, hi.x);
            o.y = pk2(lo.y, hi.y);
            o.z = pk2(lo.z, hi.z);
            o.w = pk2(lo.w, hi.w);
            W16g[(size_t)idx * 4 + q] = o;
        }
    }
    if (idx < U_ELEMS / 8) {
        const float4* p = (const float4*)u + (size_t)idx * 2;
        const float4 a = p[0], b = p[1];
        uint4 o;
        o.x = pk2(a.x, a.y); o.y = pk2(a.z, a.w);
        o.z = pk2(b.x, b.y); o.w = pk2(b.z, b.w);
        ((uint4*)u16g)[idx] = o;
    }
}

// ------------------------------ main kernel ------------------------------
__global__ void __launch_bounds__(TT, 2)
digitcaps_kernel(float* __restrict__ out)
{
    extern __shared__ uint4 uh[];              // [BT][Rc]

    const int g    = blockIdx.x;
    const int j    = blockIdx.y;
    const int b0   = g * BT;
    const int t    = threadIdx.x;
    const int warp = t >> 5;
    const int lane = t & 31;

    const uint4* __restrict__ W4  = W16g + (size_t)j * Rc * 4;
    const uint2* __restrict__ u2p = (const uint2*)u16g;

    // ====== gen: u_hat -> smem, HFMA2 math, W(k+1) prefetch, u batched ========
    {
        uint4 w0 = W4[(size_t)t * 4 + 0], w1 = W4[(size_t)t * 4 + 1];
        uint4 w2 = W4[(size_t)t * 4 + 2], w3 = W4[(size_t)t * 4 + 3];
#pragma unroll
        for (int k = 0; k < KR; k++) {
            const int r = t + k * TT;
            // prefetch next k's W row while this k's math runs
            uint4 n0, n1, n2, n3;
            if (k < KR - 1) {
                const size_t nb = (size_t)(r + TT) * 4;
                n0 = W4[nb + 0]; n1 = W4[nb + 1]; n2 = W4[nb + 2]; n3 = W4[nb + 3];
            }
            // batch all 8 u loads up front (independent LDGs)
            uint2 uu[BT];
#pragma unroll
            for (int b = 0; b < BT; b++) uu[b] = u2p[(size_t)(b0 + b) * Rc + r];
#pragma unroll
            for (int b = 0; b < BT; b++) {
                const __half2 x01 = h2(uu[b].x), x23 = h2(uu[b].y);
                const __half2 bh0 = __low2half2(x01),  bh1 = __high2half2(x01);
                const __half2 bh2 = __low2half2(x23),  bh3 = __high2half2(x23);
                uint4 pkv;
                pkv.x = u32(__hfma2(h2(w0.w), bh3, __hfma2(h2(w0.z), bh2,
                          __hfma2(h2(w0.y), bh1, __hmul2(h2(w0.x), bh0)))));
                pkv.y = u32(__hfma2(h2(w1.w), bh3, __hfma2(h2(w1.z), bh2,
                          __hfma2(h2(w1.y), bh1, __hmul2(h2(w1.x), bh0)))));
                pkv.z = u32(__hfma2(h2(w2.w), bh3, __hfma2(h2(w2.z), bh2,
                          __hfma2(h2(w2.y), bh1, __hmul2(h2(w2.x), bh0)))));
                pkv.w = u32(__hfma2(h2(w3.w), bh3, __hfma2(h2(w3.z), bh2,
                          __hfma2(h2(w3.y), bh1, __hmul2(h2(w3.x), bh0)))));
                uh[b * Rc + r] = pkv;
            }
            if (k < KR - 1) { w0 = n0; w1 = n1; w2 = n2; w3 = n3; }
        }
    }
    __syncthreads();        // the only barrier

    // ============== routing: warp b owns batch b, fully warp-private ===========
    if (warp < BT) {
        const uint4* __restrict__ base = uh + warp * Rc + lane;

        // ---- pass 0 (fp32, prefetch-4): s0 = mean_r u_hat ; v0 = squash ----
        float s[8];
#pragma unroll
        for (int q = 0; q < 8; q++) s[q] = 0.f;
        {
            uint4 buf[4];
#pragma unroll
            for (int i = 0; i < 4; i++) buf[i] = base[i * 32];
#pragma unroll
            for (int i = 0; i < RW; i++) {
                const uint4 v = buf[i & 3];
                if (i + 4 < RW) buf[i & 3] = base[(i + 4) * 32];
                const float2 f0 = up2(v.x), f1 = up2(v.y), f2 = up2(v.z), f3 = up2(v.w);
                s[0] += f0.x; s[1] += f0.y; s[2] += f1.x; s[3] += f1.y;
                s[4] += f2.x; s[5] += f2.y; s[6] += f3.x; s[7] += f3.y;
            }
        }
        wredN<8>(s);
        float v0[Oc];
        {
            float sq = 0.f;
#pragma unroll
            for (int o = 0; o < Oc; o++) { s[o] *= (1.0f / (float)Rc); sq += s[o] * s[o]; }
            const float scl = sqrtf(sq) / (1.f + sq);
#pragma unroll
            for (int o = 0; o < Oc; o++) v0[o] = s[o] * scl;
        }

        // ---- pass 1 (prefetch-4): e = exp(<uh,v0>) ; weighted sums -> v1 ----
        float p[9];
#pragma unroll
        for (int q = 0; q < 9; q++) p[q] = 0.f;
        {
            uint4 buf[4];
#pragma unroll
            for (int i = 0; i < 4; i++) buf[i] = base[i * 32];
#pragma unroll
            for (int i = 0; i < RW; i++) {
                const uint4 v = buf[i & 3];
                if (i + 4 < RW) buf[i & 3] = base[(i + 4) * 32];
                const float2 f0 = up2(v.x), f1 = up2(v.y), f2 = up2(v.z), f3 = up2(v.w);
                const float a = f0.x * v0[0] + f0.y * v0[1] + f1.x * v0[2] + f1.y * v0[3]
                              + f2.x * v0[4] + f2.y * v0[5] + f3.x * v0[6] + f3.y * v0[7];
                const float e = __expf(a);
                p[8] += e;
                p[0] += e * f0.x; p[1] += e * f0.y;
                p[2] += e * f1.x; p[3] += e * f1.y;
                p[4] += e * f2.x; p[5] += e * f2.y;
                p[6] += e * f3.x; p[7] += e * f3.y;
            }
        }
        wredN<9>(p);
        float vs[Oc];   // vs = v0 + v1  (b2 = <uh,v0> + <uh,v1> = <uh,vs>)
        {
            const float inv = 1.f / p[8];
            float sq = 0.f;
#pragma unroll
            for (int o = 0; o < Oc; o++) { p[o] *= inv; sq += p[o] * p[o]; }
            const float scl = sqrtf(sq) / (1.f + sq);
#pragma unroll
            for (int o = 0; o < Oc; o++) vs[o] = v0[o] + p[o] * scl;
        }

        // ---- pass 2 (prefetch-4): e = exp(<uh,vs>) ; weighted sums -> out ----
#pragma unroll
        for (int q = 0; q < 9; q++) p[q] = 0.f;
        {
            uint4 buf[4];
#pragma unroll
            for (int i = 0; i < 4; i++) buf[i] = base[i * 32];
#pragma unroll
            for (int i = 0; i < RW; i++) {
                const uint4 v = buf[i & 3];
                if (i + 4 < RW) buf[i & 3] = base[(i + 4) * 32];
                const float2 f0 = up2(v.x), f1 = up2(v.y), f2 = up2(v.z), f3 = up2(v.w);
                const float a = f0.x * vs[0] + f0.y * vs[1] + f1.x * vs[2] + f1.y * vs[3]
                              + f2.x * vs[4] + f2.y * vs[5] + f3.x * vs[6] + f3.y * vs[7];
                const float e = __expf(a);
                p[8] += e;
                p[0] += e * f0.x; p[1] += e * f0.y;
                p[2] += e * f1.x; p[3] += e * f1.y;
                p[4] += e * f2.x; p[5] += e * f2.y;
                p[6] += e * f3.x; p[7] += e * f3.y;
            }
        }
        wredN<9>(p);
        {
            const float inv = 1.f / p[8];
            float sq = 0.f;
#pragma unroll
            for (int o = 0; o < Oc; o++) { p[o] *= inv; sq += p[o] * p[o]; }
            const float scl = sqrtf(sq) / (1.f + sq);
            if (lane < Oc)
                out[((size_t)(b0 + warp) * Jc + j) * Oc + lane] = p[lane] * scl;
        }
    }
}

extern "C" void kernel_launch(void* const* d_in, const int* in_sizes, int n_in,
                              void* d_out, int out_size)
{
    const float* u = (const float*)d_in[0];
    const float* W = (const float*)d_in[1];
    if (n_in >= 2 && in_sizes[0] > in_sizes[1]) {   // defensive order check
        const float* tmp = u; u = W; W = tmp;
    }

    cudaFuncSetAttribute(digitcaps_kernel,
                         cudaFuncAttributeMaxDynamicSharedMemorySize, SMEM_BYTES);

    // 1) convert W (o-pair-interleaved) and u to fp16 staging buffers
    prep_kernel<<<(NROUTES + 255) / 256, 256>>>(W, u);
    // 2) fused capsule-routing kernel
    dim3 grid(Bc / BT, Jc);   // (16, 166)
    digitcaps_kernel<<<grid, TT, SMEM_BYTES>>>((float*)d_out);
}

// round 10
// speedup vs baseline: 1.3538x; 1.3538x over previous
#include <cuda_runtime.h>
#include <cuda_fp16.h>
#include <math.h>

// Problem constants
#define Jc 166
#define Rc 864
#define Oc 8
#define Bc 128
#define BT 8            // batches per CTA (one per warp, warps 0-7)
#define TT 288          // threads per CTA (864/3), 9 warps
#define KR 3            // routes per thread in gen
#define RW 27           // routes per lane in routing (864/32)

#define W_ELEMS (Jc * Rc * Oc * 4)   // 4,589,568
#define U_ELEMS (Bc * Rc * 4)        //   442,368

#define SMEM_BYTES (BT * Rc * 16)    // u_hat fp16-packed uint4: 110592 B

// fp16 copies of the inputs (static device buffers: no allocation)
__device__ __half W16g[W_ELEMS];     // 9.18 MB, layout identical to W
__device__ __half u16g[U_ELEMS];     // 0.88 MB, layout identical to u

__device__ __forceinline__ unsigned int pk2(float a, float b) {
    __half2 h = __floats2half2_rn(a, b);
    return *reinterpret_cast<unsigned int*>(&h);
}
__device__ __forceinline__ float2 up2(unsigned int v) {
    __half2 h = *reinterpret_cast<__half2*>(&v);
    return __half22float2(h);
}
__device__ __forceinline__ unsigned int hadd2u(unsigned int a, unsigned int b) {
    __half2 ha = *reinterpret_cast<__half2*>(&a);
    __half2 hb = *reinterpret_cast<__half2*>(&b);
    __half2 r = __hadd2(ha, hb);
    return *reinterpret_cast<unsigned int*>(&r);
}

// butterfly-reduce N floats across the warp (all lanes get result)
template<int N>
__device__ __forceinline__ void wredN(float* p) {
#pragma unroll
    for (int s = 16; s; s >>= 1)
#pragma unroll
        for (int q = 0; q < N; q++)
            p[q] += __shfl_xor_sync(0xffffffffu, p[q], s);
}

// one routing-route step: unpack, dot vs v, e=exp, accumulate into p[9]
__device__ __forceinline__ void route_step(const uint4 v, const float* __restrict__ vv,
                                           float* __restrict__ p) {
    const float2 f0 = up2(v.x), f1 = up2(v.y), f2 = up2(v.z), f3 = up2(v.w);
    const float a = f0.x * vv[0] + f0.y * vv[1] + f1.x * vv[2] + f1.y * vv[3]
                  + f2.x * vv[4] + f2.y * vv[5] + f3.x * vv[6] + f3.y * vv[7];
    const float e = __expf(a);
    p[8] += e;
    p[0] += e * f0.x; p[1] += e * f0.y;
    p[2] += e * f1.x; p[3] += e * f1.y;
    p[4] += e * f2.x; p[5] += e * f2.y;
    p[6] += e * f3.x; p[7] += e * f3.y;
}

// ------------------- prep: fp32 -> fp16 for W and u (R6 layout) -------------
__global__ void __launch_bounds__(256)
prep_kernel(const float* __restrict__ W, const float* __restrict__ u)
{
    const int idx = blockIdx.x * blockDim.x + threadIdx.x;
    if (idx < W_ELEMS / 8) {
        const float4* p = (const float4*)W + (size_t)idx * 2;
        const float4 a = p[0], b = p[1];
        uint4 o;
        o.x = pk2(a.x, a.y); o.y = pk2(a.z, a.w);
        o.z = pk2(b.x, b.y); o.w = pk2(b.z, b.w);
        ((uint4*)W16g)[idx] = o;
    }
    if (idx < U_ELEMS / 8) {
        const float4* p = (const float4*)u + (size_t)idx * 2;
        const float4 a = p[0], b = p[1];
        uint4 o;
        o.x = pk2(a.x, a.y); o.y = pk2(a.z, a.w);
        o.z = pk2(b.x, b.y); o.w = pk2(b.z, b.w);
        ((uint4*)u16g)[idx] = o;
    }
}

// ------------------------------ main kernel ------------------------------
__global__ void __launch_bounds__(TT, 2)
digitcaps_kernel(float* __restrict__ out)
{
    extern __shared__ uint4 uh[];              // [BT][Rc]

    const int g    = blockIdx.x;
    const int j    = blockIdx.y;
    const int b0   = g * BT;
    const int t    = threadIdx.x;
    const int warp = t >> 5;
    const int lane = t & 31;

    // W16 route r of capsule j: 32 halves = 4 uint4 at index (j*Rc + r)*4
    const uint4* __restrict__ W4 = ((const uint4*)W16g) + (size_t)j * Rc * 4;
    // u16 (b, r): 4 halves = 1 uint2 at index b*Rc + r
    const uint2* __restrict__ u2p = (const uint2*)u16g;

    // ====== gen: u_hat -> smem (fp16 packed), fp32 math (R6 verbatim) =========
#pragma unroll
    for (int k = 0; k < KR; k++) {
        const int r = t + k * TT;
        float w[Oc][4];
#pragma unroll
        for (int q = 0; q < 4; q++) {
            const uint4 wq = W4[(size_t)r * 4 + q];
            const float2 a0 = up2(wq.x), a1 = up2(wq.y);   // o = 2q
            const float2 c0 = up2(wq.z), c1 = up2(wq.w);   // o = 2q+1
            w[2 * q + 0][0] = a0.x; w[2 * q + 0][1] = a0.y;
            w[2 * q + 0][2] = a1.x; w[2 * q + 0][3] = a1.y;
            w[2 * q + 1][0] = c0.x; w[2 * q + 1][1] = c0.y;
            w[2 * q + 1][2] = c1.x; w[2 * q + 1][3] = c1.y;
        }
#pragma unroll
        for (int b = 0; b < BT; b++) {
            const uint2 uu2 = u2p[(size_t)(b0 + b) * Rc + r];
            const float2 u01 = up2(uu2.x), u23 = up2(uu2.y);
            float h[Oc];
#pragma unroll
            for (int o = 0; o < Oc; o++)
                h[o] = w[o][0] * u01.x + w[o][1] * u01.y
                     + w[o][2] * u23.x + w[o][3] * u23.y;
            uint4 pkv;
            pkv.x = pk2(h[0], h[1]);
            pkv.y = pk2(h[2], h[3]);
            pkv.z = pk2(h[4], h[5]);
            pkv.w = pk2(h[6], h[7]);
            uh[b * Rc + r] = pkv;
        }
    }
    __syncthreads();        // the only barrier

    // ============== routing: warp b owns batch b, fully warp-private ===========
    if (warp < BT) {
        const uint4* __restrict__ base = uh + warp * Rc + lane;

        // ---- pass 0 (half2 accumulate): s0 = mean_r u_hat ; v0 = squash ----
        // fp16 accumulation here only perturbs softmax weights (harmless).
        unsigned int h0 = 0u, h1 = 0u, h2v = 0u, h3 = 0u;
#pragma unroll 9
        for (int i = 0; i < RW; i++) {
            const uint4 v = base[i * 32];
            h0 = hadd2u(h0, v.x); h1 = hadd2u(h1, v.y);
            h2v = hadd2u(h2v, v.z); h3 = hadd2u(h3, v.w);
        }
#pragma unroll
        for (int s = 16; s; s >>= 1) {
            h0 = hadd2u(h0, __shfl_xor_sync(0xffffffffu, h0, s));
            h1 = hadd2u(h1, __shfl_xor_sync(0xffffffffu, h1, s));
            h2v = hadd2u(h2v, __shfl_xor_sync(0xffffffffu, h2v, s));
            h3 = hadd2u(h3, __shfl_xor_sync(0xffffffffu, h3, s));
        }
        float v0[Oc];
        {
            const float2 f0 = up2(h0), f1 = up2(h1), f2 = up2(h2v), f3 = up2(h3);
            float s[Oc] = { f0.x, f0.y, f1.x, f1.y, f2.x, f2.y, f3.x, f3.y };
            float sq = 0.f;
#pragma unroll
            for (int o = 0; o < Oc; o++) { s[o] *= (1.0f / (float)Rc); sq += s[o] * s[o]; }
            const float scl = sqrtf(sq) / (1.f + sq);
#pragma unroll
            for (int o = 0; o < Oc; o++) v0[o] = s[o] * scl;
        }

        // ---- pass 1 (2-way interleaved): e = exp(<uh,v0>); sums -> v1 ----
        float pa[9], pb[9];
#pragma unroll
        for (int q = 0; q < 9; q++) { pa[q] = 0.f; pb[q] = 0.f; }
#pragma unroll
        for (int i = 0; i < RW / 2; i++) {              // 13 pairs
            const uint4 va = base[(2 * i) * 32];
            const uint4 vb = base[(2 * i + 1) * 32];
            route_step(va, v0, pa);
            route_step(vb, v0, pb);
        }
        route_step(base[(RW - 1) * 32], v0, pa);        // tail route 26
#pragma unroll
        for (int q = 0; q < 9; q++) pa[q] += pb[q];
        wredN<9>(pa);
        float vs[Oc];   // vs = v0 + v1  (b2 = <uh,v0> + <uh,v1> = <uh,vs>)
        {
            const float inv = 1.f / pa[8];
            float sq = 0.f;
#pragma unroll
            for (int o = 0; o < Oc; o++) { pa[o] *= inv; sq += pa[o] * pa[o]; }
            const float scl = sqrtf(sq) / (1.f + sq);
#pragma unroll
            for (int o = 0; o < Oc; o++) vs[o] = v0[o] + pa[o] * scl;
        }

        // ---- pass 2 (2-way interleaved): e = exp(<uh,vs>); sums -> out ----
#pragma unroll
        for (int q = 0; q < 9; q++) { pa[q] = 0.f; pb[q] = 0.f; }
#pragma unroll
        for (int i = 0; i < RW / 2; i++) {
            const uint4 va = base[(2 * i) * 32];
            const uint4 vb = base[(2 * i + 1) * 32];
            route_step(va, vs, pa);
            route_step(vb, vs, pb);
        }
        route_step(base[(RW - 1) * 32], vs, pa);
#pragma unroll
        for (int q = 0; q < 9; q++) pa[q] += pb[q];
        wredN<9>(pa);
        {
            const float inv = 1.f / pa[8];
            float sq = 0.f;
#pragma unroll
            for (int o = 0; o < Oc; o++) { pa[o] *= inv; sq += pa[o] * pa[o]; }
            const float scl = sqrtf(sq) / (1.f + sq);
            if (lane < Oc)
                out[((size_t)(b0 + warp) * Jc + j) * Oc + lane] = pa[lane] * scl;
        }
    }
}

extern "C" void kernel_launch(void* const* d_in, const int* in_sizes, int n_in,
                              void* d_out, int out_size)
{
    const float* u = (const float*)d_in[0];
    const float* W = (const float*)d_in[1];
    if (n_in >= 2 && in_sizes[0] > in_sizes[1]) {   // defensive order check
        const float* tmp = u; u = W; W = tmp;
    }

    cudaFuncSetAttribute(digitcaps_kernel,
                         cudaFuncAttributeMaxDynamicSharedMemorySize, SMEM_BYTES);

    // 1) convert W, u to fp16 staging buffers
    prep_kernel<<<(W_ELEMS / 8 + 255) / 256, 256>>>(W, u);
    // 2) fused capsule-routing kernel
    dim3 grid(Bc / BT, Jc);   // (16, 166)
    digitcaps_kernel<<<grid, TT, SMEM_BYTES>>>((float*)d_out);
}

// round 11
// speedup vs baseline: 1.5489x; 1.1442x over previous
#include <cuda_runtime.h>
#include <cuda_fp16.h>
#include <math.h>

// Problem constants
#define Jc 166
#define Rc 864
#define Oc 8
#define Bc 128
#define BT 8            // batches per CTA (one per warp, warps 0-7)
#define TT 256          // threads per CTA (8 warps) -> 128-reg ceiling at 2 CTAs/SM
#define RW 27           // routes per lane in routing (864/32)

#define W_ELEMS (Jc * Rc * Oc * 4)   // 4,589,568
#define U_ELEMS (Bc * Rc * 4)        //   442,368

#define SMEM_BYTES (BT * Rc * 16)    // u_hat fp16-packed uint4: 110592 B

// fp16 copies of the inputs (static device buffers: no allocation)
__device__ __half W16g[W_ELEMS];     // 9.18 MB, layout identical to W
__device__ __half u16g[U_ELEMS];     // 0.88 MB, layout identical to u

__device__ __forceinline__ unsigned int pk2(float a, float b) {
    __half2 h = __floats2half2_rn(a, b);
    return *reinterpret_cast<unsigned int*>(&h);
}
__device__ __forceinline__ float2 up2(unsigned int v) {
    __half2 h = *reinterpret_cast<__half2*>(&v);
    return __half22float2(h);
}

// butterfly-reduce N floats across the warp (all lanes get result)
template<int N>
__device__ __forceinline__ void wredN(float* p) {
#pragma unroll
    for (int s = 16; s; s >>= 1)
#pragma unroll
        for (int q = 0; q < N; q++)
            p[q] += __shfl_xor_sync(0xffffffffu, p[q], s);
}

// one routing-route step: unpack, dot vs vv, e=exp, accumulate into p[9]
__device__ __forceinline__ void route_step(const uint4 v, const float* __restrict__ vv,
                                           float* __restrict__ p) {
    const float2 f0 = up2(v.x), f1 = up2(v.y), f2 = up2(v.z), f3 = up2(v.w);
    const float a = f0.x * vv[0] + f0.y * vv[1] + f1.x * vv[2] + f1.y * vv[3]
                  + f2.x * vv[4] + f2.y * vv[5] + f3.x * vv[6] + f3.y * vv[7];
    const float e = __expf(a);
    p[8] += e;
    p[0] += e * f0.x; p[1] += e * f0.y;
    p[2] += e * f1.x; p[3] += e * f1.y;
    p[4] += e * f2.x; p[5] += e * f2.y;
    p[6] += e * f3.x; p[7] += e * f3.y;
}

// ------------------- prep: fp32 -> fp16 for W and u -------------------
__global__ void __launch_bounds__(256)
prep_kernel(const float* __restrict__ W, const float* __restrict__ u)
{
    const int idx = blockIdx.x * blockDim.x + threadIdx.x;
    if (idx < W_ELEMS / 8) {
        const float4* p = (const float4*)W + (size_t)idx * 2;
        const float4 a = p[0], b = p[1];
        uint4 o;
        o.x = pk2(a.x, a.y); o.y = pk2(a.z, a.w);
        o.z = pk2(b.x, b.y); o.w = pk2(b.z, b.w);
        ((uint4*)W16g)[idx] = o;
    }
    if (idx < U_ELEMS / 8) {
        const float4* p = (const float4*)u + (size_t)idx * 2;
        const float4 a = p[0], b = p[1];
        uint4 o;
        o.x = pk2(a.x, a.y); o.y = pk2(a.z, a.w);
        o.z = pk2(b.x, b.y); o.w = pk2(b.z, b.w);
        ((uint4*)u16g)[idx] = o;
    }
}

// gen inner body for one route r: W row -> u_hat for all 8 batches
__device__ __forceinline__ void gen_route(const uint4* __restrict__ W4,
                                          const uint2* __restrict__ u2p,
                                          uint4* __restrict__ uh,
                                          int r, int b0)
{
    float w[Oc][4];
#pragma unroll
    for (int q = 0; q < 4; q++) {
        const uint4 wq = W4[(size_t)r * 4 + q];
        const float2 a0 = up2(wq.x), a1 = up2(wq.y);   // o = 2q
        const float2 c0 = up2(wq.z), c1 = up2(wq.w);   // o = 2q+1
        w[2 * q + 0][0] = a0.x; w[2 * q + 0][1] = a0.y;
        w[2 * q + 0][2] = a1.x; w[2 * q + 0][3] = a1.y;
        w[2 * q + 1][0] = c0.x; w[2 * q + 1][1] = c0.y;
        w[2 * q + 1][2] = c1.x; w[2 * q + 1][3] = c1.y;
    }
#pragma unroll
    for (int b = 0; b < BT; b++) {
        const uint2 uu2 = u2p[(size_t)(b0 + b) * Rc + r];
        const float2 u01 = up2(uu2.x), u23 = up2(uu2.y);
        float h[Oc];
#pragma unroll
        for (int o = 0; o < Oc; o++)
            h[o] = w[o][0] * u01.x + w[o][1] * u01.y
                 + w[o][2] * u23.x + w[o][3] * u23.y;
        uint4 pkv;
        pkv.x = pk2(h[0], h[1]);
        pkv.y = pk2(h[2], h[3]);
        pkv.z = pk2(h[4], h[5]);
        pkv.w = pk2(h[6], h[7]);
        uh[b * Rc + r] = pkv;
    }
}

// ------------------------------ main kernel ------------------------------
__global__ void __launch_bounds__(TT, 2)
digitcaps_kernel(float* __restrict__ out)
{
    extern __shared__ uint4 uh[];              // [BT][Rc]

    const int g    = blockIdx.x;
    const int j    = blockIdx.y;
    const int b0   = g * BT;
    const int t    = threadIdx.x;
    const int warp = t >> 5;
    const int lane = t & 31;

    const uint4* __restrict__ W4 = ((const uint4*)W16g) + (size_t)j * Rc * 4;
    const uint2* __restrict__ u2p = (const uint2*)u16g;

    // ====== gen: u_hat -> smem; 3 full iterations + 96-thread tail ============
    gen_route(W4, u2p, uh, t,            b0);
    gen_route(W4, u2p, uh, t + TT,       b0);
    gen_route(W4, u2p, uh, t + 2 * TT,   b0);
    if (t < Rc - 3 * TT)                           // 96 threads cover 768..863
        gen_route(W4, u2p, uh, t + 3 * TT, b0);
    __syncthreads();        // the only barrier

    // ============== routing: warp b owns batch b, fully warp-private ===========
    {
        const uint4* __restrict__ base = uh + warp * Rc + lane;

        // ---- pass 0 (fp32): s0 = mean_r u_hat ; v0 = squash(s0) ----
        float s[8];
#pragma unroll
        for (int q = 0; q < 8; q++) s[q] = 0.f;
#pragma unroll 9
        for (int i = 0; i < RW; i++) {
            const uint4 v = base[i * 32];
            const float2 f0 = up2(v.x), f1 = up2(v.y), f2 = up2(v.z), f3 = up2(v.w);
            s[0] += f0.x; s[1] += f0.y; s[2] += f1.x; s[3] += f1.y;
            s[4] += f2.x; s[5] += f2.y; s[6] += f3.x; s[7] += f3.y;
        }
        wredN<8>(s);
        float v0[Oc];
        {
            float sq = 0.f;
#pragma unroll
            for (int o = 0; o < Oc; o++) { s[o] *= (1.0f / (float)Rc); sq += s[o] * s[o]; }
            const float scl = sqrtf(sq) / (1.f + sq);
#pragma unroll
            for (int o = 0; o < Oc; o++) v0[o] = s[o] * scl;
        }

        // ---- pass 1 (2-way interleaved): e = exp(<uh,v0>); sums -> v1 ----
        float pa[9], pb[9];
#pragma unroll
        for (int q = 0; q < 9; q++) { pa[q] = 0.f; pb[q] = 0.f; }
#pragma unroll
        for (int i = 0; i < RW / 2; i++) {              // 13 pairs
            const uint4 va = base[(2 * i) * 32];
            const uint4 vb = base[(2 * i + 1) * 32];
            route_step(va, v0, pa);
            route_step(vb, v0, pb);
        }
        route_step(base[(RW - 1) * 32], v0, pa);        // tail route 26
#pragma unroll
        for (int q = 0; q < 9; q++) pa[q] += pb[q];
        wredN<9>(pa);
        float vs[Oc];   // vs = v0 + v1  (b2 = <uh,v0> + <uh,v1> = <uh,vs>)
        {
            const float inv = 1.f / pa[8];
            float sq = 0.f;
#pragma unroll
            for (int o = 0; o < Oc; o++) { pa[o] *= inv; sq += pa[o] * pa[o]; }
            const float scl = sqrtf(sq) / (1.f + sq);
#pragma unroll
            for (int o = 0; o < Oc; o++) vs[o] = v0[o] + pa[o] * scl;
        }

        // ---- pass 2 (2-way interleaved): e = exp(<uh,vs>); sums -> out ----
#pragma unroll
        for (int q = 0; q < 9; q++) { pa[q] = 0.f; pb[q] = 0.f; }
#pragma unroll
        for (int i = 0; i < RW / 2; i++) {
            const uint4 va = base[(2 * i) * 32];
            const uint4 vb = base[(2 * i + 1) * 32];
            route_step(va, vs, pa);
            route_step(vb, vs, pb);
        }
        route_step(base[(RW - 1) * 32], vs, pa);
#pragma unroll
        for (int q = 0; q < 9; q++) pa[q] += pb[q];
        wredN<9>(pa);
        {
            const float inv = 1.f / pa[8];
            float sq = 0.f;
#pragma unroll
            for (int o = 0; o < Oc; o++) { pa[o] *= inv; sq += pa[o] * pa[o]; }
            const float scl = sqrtf(sq) / (1.f + sq);
            if (lane < Oc)
                out[((size_t)(b0 + warp) * Jc + j) * Oc + lane] = pa[lane] * scl;
        }
    }
}

extern "C" void kernel_launch(void* const* d_in, const int* in_sizes, int n_in,
                              void* d_out, int out_size)
{
    const float* u = (const float*)d_in[0];
    const float* W = (const float*)d_in[1];
    if (n_in >= 2 && in_sizes[0] > in_sizes[1]) {   // defensive order check
        const float* tmp = u; u = W; W = tmp;
    }

    cudaFuncSetAttribute(digitcaps_kernel,
                         cudaFuncAttributeMaxDynamicSharedMemorySize, SMEM_BYTES);

    // 1) convert W, u to fp16 staging buffers
    prep_kernel<<<(W_ELEMS / 8 + 255) / 256, 256>>>(W, u);
    // 2) fused capsule-routing kernel
    dim3 grid(Bc / BT, Jc);   // (16, 166)
    digitcaps_kernel<<<grid, TT, SMEM_BYTES>>>((float*)d_out);
}

// round 12
// speedup vs baseline: 2.2882x; 1.4773x over previous
#include <cuda_runtime.h>
#include <cuda_fp16.h>
#include <math.h>

// Problem constants
#define Jc 166
#define Rc 864
#define Oc 8
#define Bc 128
#define BT 8            // batches per CTA (one per warp, warps 0-7)
#define TT 288          // threads per CTA (864/3), 9 warps
#define KR 3            // routes per thread in gen
#define RW 27           // routes per lane in routing (864/32)

#define W_ELEMS (Jc * Rc * Oc * 4)   // 4,589,568
#define U_ELEMS (Bc * Rc * 4)        //   442,368

#define SMEM_BYTES (BT * Rc * 16)    // u_hat fp16-packed uint4: 110592 B

// fp16 copies of the inputs (static device buffers: no allocation)
__device__ __half W16g[W_ELEMS];     // 9.18 MB, layout identical to W
__device__ __half u16g[U_ELEMS];     // 0.88 MB, layout identical to u

__device__ __forceinline__ unsigned int pk2(float a, float b) {
    __half2 h = __floats2half2_rn(a, b);
    return *reinterpret_cast<unsigned int*>(&h);
}
__device__ __forceinline__ float2 up2(unsigned int v) {
    __half2 h = *reinterpret_cast<__half2*>(&v);
    return __half22float2(h);
}

// butterfly-reduce N floats across the warp (all lanes get result)
template<int N>
__device__ __forceinline__ void wredN(float* p) {
#pragma unroll
    for (int s = 16; s; s >>= 1)
#pragma unroll
        for (int q = 0; q < N; q++)
            p[q] += __shfl_xor_sync(0xffffffffu, p[q], s);
}

// one routing-route step: unpack, dot vs vv, e=exp, accumulate into p[9]
__device__ __forceinline__ void route_step(const uint4 v, const float* __restrict__ vv,
                                           float* __restrict__ p) {
    const float2 f0 = up2(v.x), f1 = up2(v.y), f2 = up2(v.z), f3 = up2(v.w);
    const float a = f0.x * vv[0] + f0.y * vv[1] + f1.x * vv[2] + f1.y * vv[3]
                  + f2.x * vv[4] + f2.y * vv[5] + f3.x * vv[6] + f3.y * vv[7];
    const float e = __expf(a);
    p[8] += e;
    p[0] += e * f0.x; p[1] += e * f0.y;
    p[2] += e * f1.x; p[3] += e * f1.y;
    p[4] += e * f2.x; p[5] += e * f2.y;
    p[6] += e * f3.x; p[7] += e * f3.y;
}

// ------------------- prep: fp32 -> fp16 for W and u -------------------
__global__ void __launch_bounds__(256)
prep_kernel(const float* __restrict__ W, const float* __restrict__ u)
{
    const int idx = blockIdx.x * blockDim.x + threadIdx.x;
    if (idx < W_ELEMS / 8) {
        const float4* p = (const float4*)W + (size_t)idx * 2;
        const float4 a = p[0], b = p[1];
        uint4 o;
        o.x = pk2(a.x, a.y); o.y = pk2(a.z, a.w);
        o.z = pk2(b.x, b.y); o.w = pk2(b.z, b.w);
        ((uint4*)W16g)[idx] = o;
    }
    if (idx < U_ELEMS / 8) {
        const float4* p = (const float4*)u + (size_t)idx * 2;
        const float4 a = p[0], b = p[1];
        uint4 o;
        o.x = pk2(a.x, a.y); o.y = pk2(a.z, a.w);
        o.z = pk2(b.x, b.y); o.w = pk2(b.z, b.w);
        ((uint4*)u16g)[idx] = o;
    }
}

// ------------------------------ main kernel ------------------------------
__global__ void __launch_bounds__(TT, 2)
digitcaps_kernel(float* __restrict__ out)
{
    extern __shared__ uint4 uh[];              // [BT][Rc]

    const int g    = blockIdx.x;
    const int j    = blockIdx.y;
    const int b0   = g * BT;
    const int t    = threadIdx.x;
    const int warp = t >> 5;
    const int lane = t & 31;

    // W16 route r of capsule j: 32 halves = 4 uint4 at index (j*Rc + r)*4
    const uint4* __restrict__ W4 = ((const uint4*)W16g) + (size_t)j * Rc * 4;
    // u16 (b, r): 4 halves = 1 uint2 at index b*Rc + r
    const uint2* __restrict__ u2p = (const uint2*)u16g;

    // ====== gen: u_hat -> smem (fp16 packed), fp32 math (R6 verbatim) =========
#pragma unroll
    for (int k = 0; k < KR; k++) {
        const int r = t + k * TT;
        float w[Oc][4];
#pragma unroll
        for (int q = 0; q < 4; q++) {
            const uint4 wq = W4[(size_t)r * 4 + q];
            const float2 a0 = up2(wq.x), a1 = up2(wq.y);   // o = 2q
            const float2 c0 = up2(wq.z), c1 = up2(wq.w);   // o = 2q+1
            w[2 * q + 0][0] = a0.x; w[2 * q + 0][1] = a0.y;
            w[2 * q + 0][2] = a1.x; w[2 * q + 0][3] = a1.y;
            w[2 * q + 1][0] = c0.x; w[2 * q + 1][1] = c0.y;
            w[2 * q + 1][2] = c1.x; w[2 * q + 1][3] = c1.y;
        }
#pragma unroll
        for (int b = 0; b < BT; b++) {
            const uint2 uu2 = u2p[(size_t)(b0 + b) * Rc + r];
            const float2 u01 = up2(uu2.x), u23 = up2(uu2.y);
            float h[Oc];
#pragma unroll
            for (int o = 0; o < Oc; o++)
                h[o] = w[o][0] * u01.x + w[o][1] * u01.y
                     + w[o][2] * u23.x + w[o][3] * u23.y;
            uint4 pkv;
            pkv.x = pk2(h[0], h[1]);
            pkv.y = pk2(h[2], h[3]);
            pkv.z = pk2(h[4], h[5]);
            pkv.w = pk2(h[6], h[7]);
            uh[b * Rc + r] = pkv;
        }
    }
    __syncthreads();        // the only barrier

    // ============== routing: warp b owns batch b, fully warp-private ===========
    if (warp < BT) {
        const uint4* __restrict__ base = uh + warp * Rc + lane;

        // ---- pass 0 (fp32, R6 verbatim): s0 = mean_r u_hat ; v0 = squash ----
        float s[8];
#pragma unroll
        for (int q = 0; q < 8; q++) s[q] = 0.f;
#pragma unroll 9
        for (int i = 0; i < RW; i++) {
            const uint4 v = base[i * 32];
            const float2 f0 = up2(v.x), f1 = up2(v.y), f2 = up2(v.z), f3 = up2(v.w);
            s[0] += f0.x; s[1] += f0.y; s[2] += f1.x; s[3] += f1.y;
            s[4] += f2.x; s[5] += f2.y; s[6] += f3.x; s[7] += f3.y;
        }
        wredN<8>(s);
        float v0[Oc];
        {
            float sq = 0.f;
#pragma unroll
            for (int o = 0; o < Oc; o++) { s[o] *= (1.0f / (float)Rc); sq += s[o] * s[o]; }
            const float scl = sqrtf(sq) / (1.f + sq);
#pragma unroll
            for (int o = 0; o < Oc; o++) v0[o] = s[o] * scl;
        }

        // ---- pass 1: dual-chain interleave, NOT unrolled (no LDS hoisting) ----
        float pa[9], pb[9];
#pragma unroll
        for (int q = 0; q < 9; q++) { pa[q] = 0.f; pb[q] = 0.f; }
        {
            const uint4* qp = base;
#pragma unroll 1
            for (int i = 0; i < RW / 2; i++) {          // 13 pairs
                const uint4 va = qp[0];
                const uint4 vb = qp[32];
                route_step(va, v0, pa);
                route_step(vb, v0, pb);
                qp += 64;
            }
            route_step(qp[0], v0, pa);                  // tail route 26
        }
#pragma unroll
        for (int q = 0; q < 9; q++) pa[q] += pb[q];
        wredN<9>(pa);
        float vs[Oc];   // vs = v0 + v1  (b2 = <uh,v0> + <uh,v1> = <uh,vs>)
        {
            const float inv = 1.f / pa[8];
            float sq = 0.f;
#pragma unroll
            for (int o = 0; o < Oc; o++) { pa[o] *= inv; sq += pa[o] * pa[o]; }
            const float scl = sqrtf(sq) / (1.f + sq);
#pragma unroll
            for (int o = 0; o < Oc; o++) vs[o] = v0[o] + pa[o] * scl;
        }

        // ---- pass 2: dual-chain interleave, NOT unrolled ----
#pragma unroll
        for (int q = 0; q < 9; q++) { pa[q] = 0.f; pb[q] = 0.f; }
        {
            const uint4* qp = base;
#pragma unroll 1
            for (int i = 0; i < RW / 2; i++) {
                const uint4 va = qp[0];
                const uint4 vb = qp[32];
                route_step(va, vs, pa);
                route_step(vb, vs, pb);
                qp += 64;
            }
            route_step(qp[0], vs, pa);
        }
#pragma unroll
        for (int q = 0; q < 9; q++) pa[q] += pb[q];
        wredN<9>(pa);
        {
            const float inv = 1.f / pa[8];
            float sq = 0.f;
#pragma unroll
            for (int o = 0; o < Oc; o++) { pa[o] *= inv; sq += pa[o] * pa[o]; }
            const float scl = sqrtf(sq) / (1.f + sq);
            if (lane < Oc)
                out[((size_t)(b0 + warp) * Jc + j) * Oc + lane] = pa[lane] * scl;
        }
    }
}

extern "C" void kernel_launch(void* const* d_in, const int* in_sizes, int n_in,
                              void* d_out, int out_size)
{
    const float* u = (const float*)d_in[0];
    const float* W = (const float*)d_in[1];
    if (n_in >= 2 && in_sizes[0] > in_sizes[1]) {   // defensive order check
        const float* tmp = u; u = W; W = tmp;
    }

    cudaFuncSetAttribute(digitcaps_kernel,
                         cudaFuncAttributeMaxDynamicSharedMemorySize, SMEM_BYTES);

    // 1) convert W, u to fp16 staging buffers
    prep_kernel<<<(W_ELEMS / 8 + 255) / 256, 256>>>(W, u);
    // 2) fused capsule-routing kernel
    dim3 grid(Bc / BT, Jc);   // (16, 166)
    digitcaps_kernel<<<grid, TT, SMEM_BYTES>>>((float*)d_out);
}

// round 13
// speedup vs baseline: 2.4954x; 1.0905x over previous
#include <cuda_runtime.h>
#include <cuda_fp16.h>
#include <math.h>

// Problem constants
#define Jc 166
#define Rc 864
#define Oc 8
#define Bc 128
#define BT 8            // batches per CTA (one per warp, warps 0-7)
#define TT 288          // threads per CTA (864/3), 9 warps
#define KR 3            // routes per thread in gen
#define RW 27           // routes per lane in routing (864/32)

#define W_ELEMS (Jc * Rc * Oc * 4)   // 4,589,568
#define U_ELEMS (Bc * Rc * 4)        //   442,368

#define SMEM_BYTES (BT * Rc * 16)    // u_hat fp16-packed uint4: 110592 B
#define LOG2E 1.4426950408889634f

// fp16 copies of the inputs (static device buffers: no allocation)
__device__ __half W16g[W_ELEMS];     // 9.18 MB, layout identical to W
__device__ __half u16g[U_ELEMS];     // 0.88 MB, layout identical to u

__device__ __forceinline__ unsigned int pk2(float a, float b) {
    __half2 h = __floats2half2_rn(a, b);
    return *reinterpret_cast<unsigned int*>(&h);
}
__device__ __forceinline__ float2 up2(unsigned int v) {
    __half2 h = *reinterpret_cast<__half2*>(&v);
    return __half22float2(h);
}
__device__ __forceinline__ unsigned int hadd2u(unsigned int a, unsigned int b) {
    __half2 ha = *reinterpret_cast<__half2*>(&a);
    __half2 hb = *reinterpret_cast<__half2*>(&b);
    __half2 r = __hadd2(ha, hb);
    return *reinterpret_cast<unsigned int*>(&r);
}

// butterfly-reduce N floats across the warp (all lanes get result)
template<int N>
__device__ __forceinline__ void wredN(float* p) {
#pragma unroll
    for (int s = 16; s; s >>= 1)
#pragma unroll
        for (int q = 0; q < N; q++)
            p[q] += __shfl_xor_sync(0xffffffffu, p[q], s);
}

// ------------------- prep: fp32 -> fp16 for W and u -------------------
__global__ void __launch_bounds__(256)
prep_kernel(const float* __restrict__ W, const float* __restrict__ u)
{
    const int idx = blockIdx.x * blockDim.x + threadIdx.x;
    if (idx < W_ELEMS / 8) {
        const float4* p = (const float4*)W + (size_t)idx * 2;
        const float4 a = p[0], b = p[1];
        uint4 o;
        o.x = pk2(a.x, a.y); o.y = pk2(a.z, a.w);
        o.z = pk2(b.x, b.y); o.w = pk2(b.z, b.w);
        ((uint4*)W16g)[idx] = o;
    }
    if (idx < U_ELEMS / 8) {
        const float4* p = (const float4*)u + (size_t)idx * 2;
        const float4 a = p[0], b = p[1];
        uint4 o;
        o.x = pk2(a.x, a.y); o.y = pk2(a.z, a.w);
        o.z = pk2(b.x, b.y); o.w = pk2(b.z, b.w);
        ((uint4*)u16g)[idx] = o;
    }
}

// ------------------------------ main kernel ------------------------------
__global__ void __launch_bounds__(TT, 2)
digitcaps_kernel(float* __restrict__ out)
{
    extern __shared__ uint4 uh[];              // [BT][Rc]

    const int g    = blockIdx.x;
    const int j    = blockIdx.y;
    const int b0   = g * BT;
    const int t    = threadIdx.x;
    const int warp = t >> 5;
    const int lane = t & 31;

    // W16 route r of capsule j: 32 halves = 4 uint4 at index (j*Rc + r)*4
    const uint4* __restrict__ W4 = ((const uint4*)W16g) + (size_t)j * Rc * 4;
    // u16 (b, r): 4 halves = 1 uint2 at index b*Rc + r
    const uint2* __restrict__ u2p = (const uint2*)u16g;

    // ====== gen: u_hat -> smem (fp16 packed), fp32 math (R6 verbatim) =========
#pragma unroll
    for (int k = 0; k < KR; k++) {
        const int r = t + k * TT;
        float w[Oc][4];
#pragma unroll
        for (int q = 0; q < 4; q++) {
            const uint4 wq = W4[(size_t)r * 4 + q];
            const float2 a0 = up2(wq.x), a1 = up2(wq.y);   // o = 2q
            const float2 c0 = up2(wq.z), c1 = up2(wq.w);   // o = 2q+1
            w[2 * q + 0][0] = a0.x; w[2 * q + 0][1] = a0.y;
            w[2 * q + 0][2] = a1.x; w[2 * q + 0][3] = a1.y;
            w[2 * q + 1][0] = c0.x; w[2 * q + 1][1] = c0.y;
            w[2 * q + 1][2] = c1.x; w[2 * q + 1][3] = c1.y;
        }
#pragma unroll
        for (int b = 0; b < BT; b++) {
            const uint2 uu2 = u2p[(size_t)(b0 + b) * Rc + r];
            const float2 u01 = up2(uu2.x), u23 = up2(uu2.y);
            float h[Oc];
#pragma unroll
            for (int o = 0; o < Oc; o++)
                h[o] = w[o][0] * u01.x + w[o][1] * u01.y
                     + w[o][2] * u23.x + w[o][3] * u23.y;
            uint4 pkv;
            pkv.x = pk2(h[0], h[1]);
            pkv.y = pk2(h[2], h[3]);
            pkv.z = pk2(h[4], h[5]);
            pkv.w = pk2(h[6], h[7]);
            uh[b * Rc + r] = pkv;
        }
    }
    __syncthreads();        // the only barrier

    // ============== routing: warp b owns batch b, fully warp-private ===========
    if (warp < BT) {
        const uint4* __restrict__ base = uh + warp * Rc + lane;

        // ---- pass 0 (half2 accumulate): s0 = mean_r u_hat ; v0 = squash ----
        // fp16 accumulation only perturbs the iter-0 softmax weights (harmless).
        unsigned int h0 = 0u, h1 = 0u, h2v = 0u, h3 = 0u;
#pragma unroll 9
        for (int i = 0; i < RW; i++) {
            const uint4 v = base[i * 32];
            h0 = hadd2u(h0, v.x); h1 = hadd2u(h1, v.y);
            h2v = hadd2u(h2v, v.z); h3 = hadd2u(h3, v.w);
        }
#pragma unroll
        for (int s = 16; s; s >>= 1) {
            h0 = hadd2u(h0, __shfl_xor_sync(0xffffffffu, h0, s));
            h1 = hadd2u(h1, __shfl_xor_sync(0xffffffffu, h1, s));
            h2v = hadd2u(h2v, __shfl_xor_sync(0xffffffffu, h2v, s));
            h3 = hadd2u(h3, __shfl_xor_sync(0xffffffffu, h3, s));
        }
        float v0[Oc];    // true v0 (for vs construction)
        float v0s[Oc];   // v0 * log2(e) (for exp2-based softmax dot)
        {
            const float2 f0 = up2(h0), f1 = up2(h1), f2 = up2(h2v), f3 = up2(h3);
            float s[Oc] = { f0.x, f0.y, f1.x, f1.y, f2.x, f2.y, f3.x, f3.y };
            float sq = 0.f;
#pragma unroll
            for (int o = 0; o < Oc; o++) { s[o] *= (1.0f / (float)Rc); sq += s[o] * s[o]; }
            const float scl = sqrtf(sq) / (1.f + sq);
#pragma unroll
            for (int o = 0; o < Oc; o++) {
                v0[o]  = s[o] * scl;
                v0s[o] = v0[o] * LOG2E;
            }
        }

        // ---- pass 1: e = 2^(<uh,v0s>) ; weighted sums -> v1 (R6 form) ----
        float p[9];
#pragma unroll
        for (int q = 0; q < 9; q++) p[q] = 0.f;
#pragma unroll 9
        for (int i = 0; i < RW; i++) {
            const uint4 v = base[i * 32];
            const float2 f0 = up2(v.x), f1 = up2(v.y), f2 = up2(v.z), f3 = up2(v.w);
            const float a = f0.x * v0s[0] + f0.y * v0s[1] + f1.x * v0s[2] + f1.y * v0s[3]
                          + f2.x * v0s[4] + f2.y * v0s[5] + f3.x * v0s[6] + f3.y * v0s[7];
            const float e = exp2f(a);
            p[8] += e;
            p[0] += e * f0.x; p[1] += e * f0.y;
            p[2] += e * f1.x; p[3] += e * f1.y;
            p[4] += e * f2.x; p[5] += e * f2.y;
            p[6] += e * f3.x; p[7] += e * f3.y;
        }
        wredN<9>(p);
        float vss[Oc];  // (v0 + v1) * log2(e)   [b2 = <uh, v0+v1>]
        {
            const float inv = 1.f / p[8];
            float sq = 0.f;
#pragma unroll
            for (int o = 0; o < Oc; o++) { p[o] *= inv; sq += p[o] * p[o]; }
            const float scl = sqrtf(sq) / (1.f + sq);
#pragma unroll
            for (int o = 0; o < Oc; o++) vss[o] = (v0[o] + p[o] * scl) * LOG2E;
        }

        // ---- pass 2: e = 2^(<uh,vss>) ; weighted sums -> v2 -> out ----
#pragma unroll
        for (int q = 0; q < 9; q++) p[q] = 0.f;
#pragma unroll 9
        for (int i = 0; i < RW; i++) {
            const uint4 v = base[i * 32];
            const float2 f0 = up2(v.x), f1 = up2(v.y), f2 = up2(v.z), f3 = up2(v.w);
            const float a = f0.x * vss[0] + f0.y * vss[1] + f1.x * vss[2] + f1.y * vss[3]
                          + f2.x * vss[4] + f2.y * vss[5] + f3.x * vss[6] + f3.y * vss[7];
            const float e = exp2f(a);
            p[8] += e;
            p[0] += e * f0.x; p[1] += e * f0.y;
            p[2] += e * f1.x; p[3] += e * f1.y;
            p[4] += e * f2.x; p[5] += e * f2.y;
            p[6] += e * f3.x; p[7] += e * f3.y;
        }
        wredN<9>(p);
        {
            const float inv = 1.f / p[8];
            float sq = 0.f;
#pragma unroll
            for (int o = 0; o < Oc; o++) { p[o] *= inv; sq += p[o] * p[o]; }
            const float scl = sqrtf(sq) / (1.f + sq);
            if (lane < Oc)
                out[((size_t)(b0 + warp) * Jc + j) * Oc + lane] = p[lane] * scl;
        }
    }
}

extern "C" void kernel_launch(void* const* d_in, const int* in_sizes, int n_in,
                              void* d_out, int out_size)
{
    const float* u = (const float*)d_in[0];
    const float* W = (const float*)d_in[1];
    if (n_in >= 2 && in_sizes[0] > in_sizes[1]) {   // defensive order check
        const float* tmp = u; u = W; W = tmp;
    }

    cudaFuncSetAttribute(digitcaps_kernel,
                         cudaFuncAttributeMaxDynamicSharedMemorySize, SMEM_BYTES);

    // 1) convert W, u to fp16 staging buffers
    prep_kernel<<<(W_ELEMS / 8 + 255) / 256, 256>>>(W, u);
    // 2) fused capsule-routing kernel
    dim3 grid(Bc / BT, Jc);   // (16, 166)
    digitcaps_kernel<<<grid, TT, SMEM_BYTES>>>((float*)d_out);
}